// round 1
// baseline (speedup 1.0000x reference)
#include <cuda_runtime.h>
#include <cuda_bf16.h>
#include <cfloat>

// Problem constants (fixed by the dataset)
#define N_Q     2048
#define M_ROWS  100000
#define DIMS    128
#define KNN     5

// Tiling
#define NSLICES   9
#define SLICE_LEN 11112      // ceil(100000/9); 9*11112 >= 100000
#define QT        64         // queries per block tile
#define RT        128        // bank rows per block tile
#define QS_STRIDE 132        // 128 + 4 pad words -> conflict-free LDS.128

// Scratch (no cudaMalloc allowed)
__device__ float g_x2[N_Q];
__device__ float g_y2[M_ROWS];
__device__ float g_part[NSLICES][N_Q][KNN];

// ---------------------------------------------------------------------------
// Row squared-norms: one warp per row, float4 loads, shuffle reduce.
__global__ void norms_kernel(const float* __restrict__ src, int rows, int which) {
    int w    = (blockIdx.x * blockDim.x + threadIdx.x) >> 5;
    int lane = threadIdx.x & 31;
    if (w >= rows) return;
    const float4* p = reinterpret_cast<const float4*>(src + (size_t)w * DIMS);
    float4 v = p[lane];
    float s = v.x*v.x + v.y*v.y + v.z*v.z + v.w*v.w;
    #pragma unroll
    for (int o = 16; o; o >>= 1) s += __shfl_xor_sync(0xffffffffu, s, o);
    if (lane == 0) {
        if (which) g_x2[w] = s;
        else       g_y2[w] = s;
    }
}

// ---------------------------------------------------------------------------
// Main fused GEMM + top-5 kernel.
// Grid: (N_Q/QT, NSLICES). Block: 256 threads as 16(ty) x 16(tx).
// Thread tile: 4 queries (q = ty + 16*i) x 8 rows (r = tx + 16*j).
__global__ void __launch_bounds__(256, 2)
knn_main_kernel(const float* __restrict__ F, const float* __restrict__ B) {
    extern __shared__ float sm[];
    float* Qs  = sm;                       // QT * QS_STRIDE
    float* Ys  = sm + QT * QS_STRIDE;      // RT * QS_STRIDE
    float* x2s = Ys + RT * QS_STRIDE;      // QT
    float* y2s = x2s + QT;                 // RT

    const int tid = threadIdx.x;
    const int tx  = tid & 15;
    const int ty  = tid >> 4;
    const int qblock  = blockIdx.x * QT;
    const int row_beg = blockIdx.y * SLICE_LEN;
    const int row_end = min(row_beg + SLICE_LEN, M_ROWS);

    // Stage Q tile (64 x 128) once per block, coalesced float4.
    #pragma unroll
    for (int l = 0; l < (QT * (DIMS/4)) / 256; l++) {
        int idx = tid + 256 * l;           // 0..2047
        int r = idx >> 5, c = idx & 31;
        float4 v = reinterpret_cast<const float4*>(F + (size_t)(qblock + r) * DIMS)[c];
        *reinterpret_cast<float4*>(Qs + r * QS_STRIDE + c * 4) = v;
    }
    if (tid < QT) x2s[tid] = g_x2[qblock + tid];

    // Per-thread sorted (ascending) top-5 of d^2, per owned query.
    float top[4][KNN];
    #pragma unroll
    for (int i = 0; i < 4; i++)
        #pragma unroll
        for (int k = 0; k < KNN; k++) top[i][k] = FLT_MAX;

    for (int tb = row_beg; tb < row_end; tb += RT) {
        __syncthreads();
        // Stage Y tile (128 x 128), zero-fill out-of-range rows.
        #pragma unroll
        for (int l = 0; l < (RT * (DIMS/4)) / 256; l++) {
            int idx = tid + 256 * l;       // 0..4095
            int r = idx >> 5, c = idx & 31;
            int rg = tb + r;
            float4 v = make_float4(0.f, 0.f, 0.f, 0.f);
            if (rg < row_end)
                v = reinterpret_cast<const float4*>(B + (size_t)rg * DIMS)[c];
            *reinterpret_cast<float4*>(Ys + r * QS_STRIDE + c * 4) = v;
        }
        if (tid < RT) {
            int rg = tb + tid;
            y2s[tid] = (rg < row_end) ? g_y2[rg] : 0.f;
        }
        __syncthreads();

        // 4x8 register tile of dot products, float4 over k.
        float acc[4][8];
        #pragma unroll
        for (int i = 0; i < 4; i++)
            #pragma unroll
            for (int j = 0; j < 8; j++) acc[i][j] = 0.f;

        #pragma unroll 4
        for (int k = 0; k < DIMS; k += 4) {
            float4 b[8];
            #pragma unroll
            for (int j = 0; j < 8; j++)
                b[j] = *reinterpret_cast<const float4*>(Ys + (tx + 16*j) * QS_STRIDE + k);
            #pragma unroll
            for (int i = 0; i < 4; i++) {
                float4 a = *reinterpret_cast<const float4*>(Qs + (ty + 16*i) * QS_STRIDE + k);
                #pragma unroll
                for (int j = 0; j < 8; j++) {
                    acc[i][j] = fmaf(a.x, b[j].x, acc[i][j]);
                    acc[i][j] = fmaf(a.y, b[j].y, acc[i][j]);
                    acc[i][j] = fmaf(a.z, b[j].z, acc[i][j]);
                    acc[i][j] = fmaf(a.w, b[j].w, acc[i][j]);
                }
            }
        }

        // Fused top-5 update on d^2 = x2 + y2 - 2*dot.
        #pragma unroll
        for (int i = 0; i < 4; i++) {
            float x2 = x2s[ty + 16*i];
            #pragma unroll
            for (int j = 0; j < 8; j++) {
                int rg   = tb + tx + 16*j;
                float d2 = x2 + y2s[tx + 16*j] - 2.f * acc[i][j];
                if (rg < row_end && d2 < top[i][KNN-1]) {
                    top[i][KNN-1] = d2;
                    #pragma unroll
                    for (int k5 = KNN-1; k5 > 0; k5--) {
                        if (top[i][k5] < top[i][k5-1]) {
                            float t = top[i][k5-1];
                            top[i][k5-1] = top[i][k5];
                            top[i][k5]   = t;
                        }
                    }
                }
            }
        }
    }

    __syncthreads();
    // Block merge across tx-groups: reuse Ys as merge buffer [QT][16][KNN].
    float* mb = Ys;
    #pragma unroll
    for (int i = 0; i < 4; i++) {
        int q = ty + 16*i;
        #pragma unroll
        for (int k = 0; k < KNN; k++)
            mb[(q * 16 + tx) * KNN + k] = top[i][k];
    }
    __syncthreads();
    if (tid < QT) {
        int q = tid;
        float best[KNN];
        #pragma unroll
        for (int k = 0; k < KNN; k++) best[k] = FLT_MAX;
        for (int t = 0; t < 16; t++) {
            #pragma unroll
            for (int k = 0; k < KNN; k++) {
                float v = mb[(q * 16 + t) * KNN + k];
                if (v < best[KNN-1]) {
                    best[KNN-1] = v;
                    #pragma unroll
                    for (int k5 = KNN-1; k5 > 0; k5--) {
                        if (best[k5] < best[k5-1]) {
                            float tt = best[k5-1]; best[k5-1] = best[k5]; best[k5] = tt;
                        }
                    }
                }
            }
        }
        #pragma unroll
        for (int k = 0; k < KNN; k++)
            g_part[blockIdx.y][qblock + q][k] = best[k];
    }
}

// ---------------------------------------------------------------------------
// Merge slices, sqrt, min-max normalize, mean.
__global__ void finalize_kernel(const float* __restrict__ minv,
                                const float* __restrict__ maxv,
                                float* __restrict__ out) {
    int q = blockIdx.x * blockDim.x + threadIdx.x;
    if (q >= N_Q) return;
    float best[KNN];
    #pragma unroll
    for (int k = 0; k < KNN; k++) best[k] = FLT_MAX;
    for (int s = 0; s < NSLICES; s++) {
        #pragma unroll
        for (int k = 0; k < KNN; k++) {
            float v = g_part[s][q][k];
            if (v < best[KNN-1]) {
                best[KNN-1] = v;
                #pragma unroll
                for (int k5 = KNN-1; k5 > 0; k5--) {
                    if (best[k5] < best[k5-1]) {
                        float t = best[k5-1]; best[k5-1] = best[k5]; best[k5] = t;
                    }
                }
            }
        }
    }
    float mn = *minv, mx = *maxv;
    float inv = 1.f / (mx - mn);
    float sum = 0.f;
    #pragma unroll
    for (int k = 0; k < KNN; k++)
        sum += (sqrtf(fmaxf(best[k], 0.f)) - mn) * inv;
    out[q] = sum * (1.0f / KNN);
}

// ---------------------------------------------------------------------------
extern "C" void kernel_launch(void* const* d_in, const int* in_sizes, int n_in,
                              void* d_out, int out_size) {
    const float* F    = (const float*)d_in[0];   // features   (2048 x 128)
    const float* B    = (const float*)d_in[1];   // memory     (100000 x 128)
    const float* minv = (const float*)d_in[2];   // scalar
    const float* maxv = (const float*)d_in[3];   // scalar
    float* out = (float*)d_out;

    static bool attr_done = false;
    const int smem_bytes = (QT * QS_STRIDE + RT * QS_STRIDE + QT + RT) * (int)sizeof(float);
    if (!attr_done) {
        cudaFuncSetAttribute(knn_main_kernel,
                             cudaFuncAttributeMaxDynamicSharedMemorySize, smem_bytes);
        attr_done = true;
    }

    // Norms: warp per row, 8 warps per 256-thread block.
    norms_kernel<<<(M_ROWS + 7) / 8, 256>>>(B, M_ROWS, 0);
    norms_kernel<<<(N_Q    + 7) / 8, 256>>>(F, N_Q, 1);

    dim3 grid(N_Q / QT, NSLICES);
    knn_main_kernel<<<grid, 256, smem_bytes>>>(F, B);

    finalize_kernel<<<(N_Q + 255) / 256, 256>>>(minv, maxv, out);
}

// round 3
// speedup vs baseline: 2.0298x; 2.0298x over previous
#include <cuda_runtime.h>
#include <cuda_bf16.h>
#include <cstdint>
#include <cfloat>

#define N_Q     2048
#define M_ROWS  100000
#define DIMS    128
#define KNN     5

#define NSLICES   9
#define TILE_R    128
#define NTILES    87
#define SLICE_LEN (NTILES * TILE_R)   // 11136; 9*11136 >= 100000
#define QT        128                  // queries per CTA
#define TPB       256                  // 8 warps

#define TPQ       16                   // candidates kept per (query, slice)
#define RSEL      16                   // exact-refined candidates per query

// ---- device scratch ----
__device__ __nv_bfloat16 g_hiF2[N_Q * DIMS];     // bf16(-2*F)
__device__ __nv_bfloat16 g_hiB [M_ROWS * DIMS];  // bf16(B)
__device__ float g_y2[M_ROWS];
__device__ float g_cand_val[NSLICES][N_Q][TPQ];
__device__ int   g_cand_idx[NSLICES][N_Q][TPQ];

// ---- smem layout (bytes). A/B rows padded to 272B (+16) -> conflict-free LDSM
#define A_STRIDE_B 272
#define SM_A    0
#define SM_B0   (SM_A + 128 * A_STRIDE_B)          // 34816
#define SM_B1   (SM_B0 + 128 * A_STRIDE_B)         // 69632
#define SM_Y2   (SM_B1 + 128 * A_STRIDE_B)         // 104448, float[2][128]
#define SM_D    (SM_Y2 + 2 * 128 * 4)              // 105472
#define D_STRIDE_W 132                              // words
#define SMEM_TOTAL (SM_D + 128 * D_STRIDE_W * 4)   // 173056

// ---------------------------------------------------------------------------
__device__ __forceinline__ uint32_t s2u(const void* p) {
    uint32_t a;
    asm("{ .reg .u64 t; cvta.to.shared.u64 t, %1; cvt.u32.u64 %0, t; }" : "=r"(a) : "l"(p));
    return a;
}
__device__ __forceinline__ void cp16(uint32_t dst, const void* src) {
    asm volatile("cp.async.cg.shared.global [%0], [%1], 16;" :: "r"(dst), "l"(src) : "memory");
}
__device__ __forceinline__ void ldsm_x4(uint32_t& r0, uint32_t& r1, uint32_t& r2, uint32_t& r3,
                                        uint32_t addr) {
    asm volatile("ldmatrix.sync.aligned.m8n8.x4.shared.b16 {%0,%1,%2,%3}, [%4];"
                 : "=r"(r0), "=r"(r1), "=r"(r2), "=r"(r3) : "r"(addr));
}
__device__ __forceinline__ void mma16816(float& d0, float& d1, float& d2, float& d3,
                                         uint32_t a0, uint32_t a1, uint32_t a2, uint32_t a3,
                                         uint32_t b0, uint32_t b1) {
    asm volatile("mma.sync.aligned.m16n8k16.row.col.f32.bf16.bf16.f32 "
                 "{%0,%1,%2,%3}, {%4,%5,%6,%7}, {%8,%9}, {%0,%1,%2,%3};"
                 : "+f"(d0), "+f"(d1), "+f"(d2), "+f"(d3)
                 : "r"(a0), "r"(a1), "r"(a2), "r"(a3), "r"(b0), "r"(b1));
}

// ---------------------------------------------------------------------------
// Convert: bf16(B) rows, bf16(-2*F) rows, y2 norms. One warp per row.
__global__ void convert_kernel(const float* __restrict__ F, const float* __restrict__ B) {
    int gw   = (blockIdx.x * blockDim.x + threadIdx.x) >> 5;
    int lane = threadIdx.x & 31;
    if (gw >= N_Q + M_ROWS) return;
    bool isF = gw < N_Q;
    int row  = isF ? gw : gw - N_Q;
    const float* src = (isF ? F : B) + (size_t)row * DIMS;
    float4 v = reinterpret_cast<const float4*>(src)[lane];
    if (!isF) {
        float s = v.x*v.x + v.y*v.y + v.z*v.z + v.w*v.w;
        #pragma unroll
        for (int o = 16; o; o >>= 1) s += __shfl_xor_sync(0xffffffffu, s, o);
        if (lane == 0) g_y2[row] = s;
    }
    float sc = isF ? -2.0f : 1.0f;
    __nv_bfloat162 p0{__float2bfloat16_rn(sc * v.x), __float2bfloat16_rn(sc * v.y)};
    __nv_bfloat162 p1{__float2bfloat16_rn(sc * v.z), __float2bfloat16_rn(sc * v.w)};
    __nv_bfloat162* hp = reinterpret_cast<__nv_bfloat162*>(isF ? g_hiF2 : g_hiB);
    hp[(size_t)row * 64 + 2 * lane]     = p0;
    hp[(size_t)row * 64 + 2 * lane + 1] = p1;
}

// ---------------------------------------------------------------------------
// Main: mma.sync bf16 GEMM + approx top-8 per (query, half) with indices.
__global__ void __launch_bounds__(TPB, 1)
knn_mma_kernel() {
    extern __shared__ char smem[];
    const uint32_t sb = s2u(smem);
    float* y2s = reinterpret_cast<float*>(smem + SM_Y2);
    float* sD  = reinterpret_cast<float*>(smem + SM_D);

    const int tid  = threadIdx.x;
    const int wid  = tid >> 5;
    const int lane = tid & 31;
    const int wm   = wid & 3;        // 4 m-chunks of 32 rows
    const int wn   = wid >> 2;       // 2 n-chunks of 64 cols
    const int qblock  = blockIdx.x * QT;
    const int slice   = blockIdx.y;
    const int row_beg = slice * SLICE_LEN;

    // Stage A (queries), 2048 16B-chunks, 8 per thread.
    #pragma unroll
    for (int i = 0; i < 8; i++) {
        int chunk = tid + TPB * i;
        int r = chunk >> 4, cc = chunk & 15;
        uint4 v = *reinterpret_cast<const uint4*>(
            reinterpret_cast<const char*>(g_hiF2) + ((size_t)(qblock + r) * 256 + cc * 16));
        *reinterpret_cast<uint4*>(smem + SM_A + r * A_STRIDE_B + cc * 16) = v;
    }

    // Prefetch tile 0 into buffer 0.
    {
        int tb = row_beg;
        #pragma unroll
        for (int i = 0; i < 8; i++) {
            int chunk = tid + TPB * i;
            int r = chunk >> 4, cc = chunk & 15;
            int rg = tb + r;
            int rc = rg < M_ROWS ? rg : M_ROWS - 1;
            cp16(sb + SM_B0 + r * A_STRIDE_B + cc * 16,
                 reinterpret_cast<const char*>(g_hiB) + ((size_t)rc * 256 + cc * 16));
        }
        if (tid < 128) {
            int rg = tb + tid;
            y2s[tid] = (rg < M_ROWS) ? g_y2[rg] : FLT_MAX;
        }
        asm volatile("cp.async.commit_group;" ::: "memory");
    }

    // Per-thread approx top-8 (ascending) with indices; thread owns (q = tid>>1, half = tid&1).
    float tv[8]; int tix[8];
    #pragma unroll
    for (int k = 0; k < 8; k++) { tv[k] = FLT_MAX; tix[k] = -1; }
    const int sq = tid >> 1;       // scanned query (local)
    const int sh = tid & 1;        // half: cols [sh*64, sh*64+64)

    for (int t = 0; t < NTILES; t++) {
        const int buf = t & 1;
        const uint32_t Bb = sb + (buf ? SM_B1 : SM_B0);

        __syncthreads();   // prev GEMM readers of other buffer + prev scan done

        if (t + 1 < NTILES) {
            int tb = row_beg + (t + 1) * TILE_R;
            uint32_t Bn = sb + (buf ? SM_B0 : SM_B1);
            #pragma unroll
            for (int i = 0; i < 8; i++) {
                int chunk = tid + TPB * i;
                int r = chunk >> 4, cc = chunk & 15;
                int rg = tb + r;
                int rc = rg < M_ROWS ? rg : M_ROWS - 1;
                cp16(Bn + r * A_STRIDE_B + cc * 16,
                     reinterpret_cast<const char*>(g_hiB) + ((size_t)rc * 256 + cc * 16));
            }
            if (tid < 128) {
                int rg = tb + tid;
                y2s[(buf ^ 1) * 128 + tid] = (rg < M_ROWS) ? g_y2[rg] : FLT_MAX;
            }
            asm volatile("cp.async.commit_group;" ::: "memory");
            asm volatile("cp.async.wait_group 1;" ::: "memory");
        } else {
            asm volatile("cp.async.wait_group 0;" ::: "memory");
        }
        __syncthreads();   // buffer t visible CTA-wide

        // ---- GEMM: warp tile 32(q) x 64(r), K=128
        float acc[2][8][4];
        #pragma unroll
        for (int mt = 0; mt < 2; mt++)
            #pragma unroll
            for (int nt = 0; nt < 8; nt++)
                #pragma unroll
                for (int e = 0; e < 4; e++) acc[mt][nt][e] = 0.f;

        const uint32_t Abase = sb + SM_A + (wm * 32) * A_STRIDE_B;
        const uint32_t Bbase = Bb + (wn * 64) * A_STRIDE_B;
        const int arow = lane & 15;
        const int acol = (lane >> 4) * 16;
        const int brow = (lane & 7) + (lane >> 4) * 8;
        const int bcol = ((lane >> 3) & 1) * 16;

        #pragma unroll
        for (int ks = 0; ks < 8; ks++) {
            uint32_t a[2][4];
            #pragma unroll
            for (int mt = 0; mt < 2; mt++)
                ldsm_x4(a[mt][0], a[mt][1], a[mt][2], a[mt][3],
                        Abase + (mt * 16 + arow) * A_STRIDE_B + ks * 32 + acol);
            uint32_t b[8][2];
            #pragma unroll
            for (int nt2 = 0; nt2 < 4; nt2++) {
                uint32_t r0, r1, r2, r3;
                ldsm_x4(r0, r1, r2, r3,
                        Bbase + (nt2 * 16 + brow) * A_STRIDE_B + ks * 32 + bcol);
                b[nt2 * 2][0] = r0; b[nt2 * 2][1] = r1;
                b[nt2 * 2 + 1][0] = r2; b[nt2 * 2 + 1][1] = r3;
            }
            #pragma unroll
            for (int mt = 0; mt < 2; mt++)
                #pragma unroll
                for (int nt = 0; nt < 8; nt++)
                    mma16816(acc[mt][nt][0], acc[mt][nt][1], acc[mt][nt][2], acc[mt][nt][3],
                             a[mt][0], a[mt][1], a[mt][2], a[mt][3],
                             b[nt][0], b[nt][1]);
        }

        // ---- write s = acc + y2 into D exchange buffer
        const float* y2t = y2s + buf * 128;
        #pragma unroll
        for (int mt = 0; mt < 2; mt++) {
            int row0 = wm * 32 + mt * 16 + (lane >> 2);
            #pragma unroll
            for (int nt = 0; nt < 8; nt++) {
                int col = wn * 64 + nt * 8 + 2 * (lane & 3);
                float2 y2p = *reinterpret_cast<const float2*>(y2t + col);
                float2 v0{acc[mt][nt][0] + y2p.x, acc[mt][nt][1] + y2p.y};
                float2 v1{acc[mt][nt][2] + y2p.x, acc[mt][nt][3] + y2p.y};
                *reinterpret_cast<float2*>(sD + row0 * D_STRIDE_W + col)       = v0;
                *reinterpret_cast<float2*>(sD + (row0 + 8) * D_STRIDE_W + col) = v1;
            }
        }
        __syncthreads();

        // ---- scan: 64 candidates for (sq, sh)
        const int idx_base = row_beg + t * TILE_R + sh * 64;
        const float4* rowp = reinterpret_cast<const float4*>(sD + sq * D_STRIDE_W + sh * 64);
        #pragma unroll
        for (int j = 0; j < 16; j++) {
            float4 v = rowp[j];
            float vv[4] = {v.x, v.y, v.z, v.w};
            #pragma unroll
            for (int c = 0; c < 4; c++) {
                float val = vv[c];
                if (val < tv[7]) {
                    tv[7] = val; tix[7] = idx_base + 4 * j + c;
                    #pragma unroll
                    for (int k = 7; k > 0; k--) {
                        if (tv[k] < tv[k - 1]) {
                            float tf = tv[k - 1]; tv[k - 1] = tv[k]; tv[k] = tf;
                            int   ti = tix[k - 1]; tix[k - 1] = tix[k]; tix[k] = ti;
                        }
                    }
                }
            }
        }
    }

    // Write candidates.
    #pragma unroll
    for (int k = 0; k < 8; k++) {
        g_cand_val[slice][qblock + sq][sh * 8 + k] = tv[k];
        g_cand_idx[slice][qblock + sq][sh * 8 + k] = tix[k];
    }
}

// ---------------------------------------------------------------------------
// Refine: per query (one warp): approx-top-16 of 144 candidates -> exact fp32
// distances -> top-5 -> sqrt, normalize, mean.
__global__ void __launch_bounds__(256)
refine_kernel(const float* __restrict__ F, const float* __restrict__ B,
              const float* __restrict__ minv, const float* __restrict__ maxv,
              float* __restrict__ out) {
    __shared__ float sv[8][NSLICES * TPQ];
    __shared__ int   si[8][NSLICES * TPQ];
    __shared__ int   sel[8][RSEL];
    __shared__ float ex[8][RSEL];

    const int w    = threadIdx.x >> 5;
    const int lane = threadIdx.x & 31;
    const int q    = blockIdx.x * 8 + w;
    const int NC   = NSLICES * TPQ;   // 144

    for (int i = lane; i < NC; i += 32) {
        sv[w][i] = g_cand_val[i / TPQ][q][i % TPQ];
        si[w][i] = g_cand_idx[i / TPQ][q][i % TPQ];
    }
    __syncwarp();

    // Query vector + exact x2.
    float4 xv = reinterpret_cast<const float4*>(F + (size_t)q * DIMS)[lane];
    float x2 = xv.x*xv.x + xv.y*xv.y + xv.z*xv.z + xv.w*xv.w;
    #pragma unroll
    for (int o = 16; o; o >>= 1) x2 += __shfl_xor_sync(0xffffffffu, x2, o);

    // Rank-select approx top-RSEL (strict order via (val, pos)).
    for (int i = lane; i < NC; i += 32) {
        float v = sv[w][i];
        int r = 0;
        for (int j = 0; j < NC; j++) {
            float u = sv[w][j];
            r += (u < v) || (u == v && j < i);
        }
        if (r < RSEL) sel[w][r] = si[w][i];
    }
    __syncwarp();

    // Exact distances for the selected candidates.
    for (int c = 0; c < RSEL; c++) {
        int id = sel[w][c];
        float d2 = FLT_MAX;
        if (id >= 0) {
            float4 yv = reinterpret_cast<const float4*>(B + (size_t)id * DIMS)[lane];
            float p = yv.x*yv.x + yv.y*yv.y + yv.z*yv.z + yv.w*yv.w
                    - 2.0f * (xv.x*yv.x + xv.y*yv.y + xv.z*yv.z + xv.w*yv.w);
            #pragma unroll
            for (int o = 16; o; o >>= 1) p += __shfl_xor_sync(0xffffffffu, p, o);
            d2 = x2 + p;
        }
        if (lane == 0) ex[w][c] = d2;
    }
    __syncwarp();

    if (lane == 0) {
        float best[KNN];
        #pragma unroll
        for (int k = 0; k < KNN; k++) best[k] = FLT_MAX;
        #pragma unroll
        for (int c = 0; c < RSEL; c++) {
            float v = ex[w][c];
            if (v < best[KNN - 1]) {
                best[KNN - 1] = v;
                #pragma unroll
                for (int k = KNN - 1; k > 0; k--) {
                    if (best[k] < best[k - 1]) {
                        float tf = best[k - 1]; best[k - 1] = best[k]; best[k] = tf;
                    }
                }
            }
        }
        float mn = *minv, mx = *maxv;
        float inv = 1.f / (mx - mn);
        float sum = 0.f;
        #pragma unroll
        for (int k = 0; k < KNN; k++)
            sum += (sqrtf(fmaxf(best[k], 0.f)) - mn) * inv;
        out[q] = sum * (1.0f / KNN);
    }
}

// ---------------------------------------------------------------------------
extern "C" void kernel_launch(void* const* d_in, const int* in_sizes, int n_in,
                              void* d_out, int out_size) {
    const float* F    = (const float*)d_in[0];
    const float* B    = (const float*)d_in[1];
    const float* minv = (const float*)d_in[2];
    const float* maxv = (const float*)d_in[3];
    float* out = (float*)d_out;

    static bool attr_done = false;
    if (!attr_done) {
        cudaFuncSetAttribute(knn_mma_kernel,
                             cudaFuncAttributeMaxDynamicSharedMemorySize, SMEM_TOTAL);
        attr_done = true;
    }

    int conv_blocks = ((N_Q + M_ROWS) * 32 + 255) / 256;
    convert_kernel<<<conv_blocks, 256>>>(F, B);

    dim3 grid(N_Q / QT, NSLICES);
    knn_mma_kernel<<<grid, TPB, SMEM_TOTAL>>>();

    refine_kernel<<<N_Q / 8, 256>>>(F, B, minv, maxv, out);
}